// round 14
// baseline (speedup 1.0000x reference)
#include <cuda_runtime.h>
#include <math_constants.h>
#include <cstdint>

#define BATCH 4
#define SEQ   4096
#define DIN   768
#define DH    64
#define MTOT  (BATCH*SEQ)
#define SPLIT 4

// Scratch (no cudaMalloc allowed)
// g_k fragment-stream layout per 64-key tile (4096 floats):
//   K element (key,d):  stream=(key&7)*4+(d&3),  pos=(d>>3)*16+((key&63)>>3)*2+((d>>2)&1)
// g_v: same but keys PERMUTED within each 8-group so the S accumulator is
//   directly the PV A-fragment: slot k for key: k = (key&1)? (key+7)>>1 : key>>1
//   V element (key,dh): stream=(dh&7)*4+(kslot&3), pos=((key&63)>>3)*16+(dh>>3)*2+((kslot>>2)&1)
__device__ float g_q[MTOT*DH];
__device__ float g_k[MTOT*DH];
__device__ float g_v[MTOT*DH];           // RNA-tf32 at producer
__device__ float g_wc[3][DIN*DH];        // RNA-tf32 weights, fragment-stream layout
__device__ float g_po[SPLIT][MTOT*DH];
__device__ float g_pl[SPLIT][MTOT];

__device__ __forceinline__ float tf32r(float x) {
    float r;
    asm("cvt.rna.tf32.f32 %0, %1;" : "=f"(r) : "f"(x));
    return r;
}

__device__ __forceinline__ void mma_tf32(float c[4],
                                         uint32_t a0, uint32_t a1, uint32_t a2, uint32_t a3,
                                         uint32_t b0, uint32_t b1) {
    asm volatile(
        "mma.sync.aligned.m16n8k8.row.col.f32.tf32.tf32.f32 "
        "{%0,%1,%2,%3},{%4,%5,%6,%7},{%8,%9},{%0,%1,%2,%3};\n"
        : "+f"(c[0]), "+f"(c[1]), "+f"(c[2]), "+f"(c[3])
        : "r"(a0), "r"(a1), "r"(a2), "r"(a3), "r"(b0), "r"(b1));
}

__device__ __forceinline__ void mma_tf32f(float c[4],
                                          float a0, float a1, float a2, float a3,
                                          uint32_t b0, uint32_t b1) {
    mma_tf32(c, __float_as_uint(a0), __float_as_uint(a1),
                __float_as_uint(a2), __float_as_uint(a3), b0, b1);
}

__device__ __forceinline__ void cp16(uint32_t dst, const float* src) {
    asm volatile("cp.async.ca.shared.global [%0], [%1], 16;\n" :: "r"(dst), "l"(src));
}
__device__ __forceinline__ void cp_commit() {
    asm volatile("cp.async.commit_group;\n");
}
__device__ __forceinline__ void cp_wait0() {
    asm volatile("cp.async.wait_group 0;\n" ::: "memory");
}
__device__ __forceinline__ void cp_wait1() {
    asm volatile("cp.async.wait_group 1;\n" ::: "memory");
}

// ----------------------------------------------------------------------------
// Weight pre-conversion + fragment-stream re-layout (unchanged).
// ----------------------------------------------------------------------------
__global__ __launch_bounds__(256)
void wconv_kernel(const float* __restrict__ wq,
                  const float* __restrict__ wk,
                  const float* __restrict__ wv)
{
    int i = blockIdx.x * 256 + threadIdx.x;
    const float* __restrict__ src[3] = {wq, wk, wv};
    int k  = i >> 6;
    int n  = i & 63;
    int kt = k >> 5, kk = k & 31;
    int ks = kk >> 3, t4w = kk & 3, bb = (kk >> 2) & 1;
    int wn = n >> 5, gg = n & 7, nt = (n >> 3) & 3;
    size_t dst = (size_t)kt*2048 + (size_t)(wn*32 + gg*4 + t4w)*32 + ks*8 + nt*2 + bb;
    #pragma unroll
    for (int m = 0; m < 3; ++m)
        g_wc[m][dst] = tf32r(src[m][i]);
}

// ----------------------------------------------------------------------------
// QKV projection (r12 pipeline). V epilogue scatter uses the PERMUTED key-slot
// layout so attn's S-accumulators serve directly as PV A-fragments.
// ----------------------------------------------------------------------------
#define QBM 64
#define QBK 32
#define QNT (DIN/QBK)
#define LX  36
#define XSTG (QBM*LX)
#define WMTX (64*36)
#define WSTG (3*WMTX)
#define XTOT (3*XSTG)
#define QKV_SMEM_FLOATS (XTOT + 2*WSTG)
#define QKV_SMEM_BYTES  (QKV_SMEM_FLOATS*4)

__global__ __launch_bounds__(256)
void qkv_gemm_kernel(const float* __restrict__ X)
{
    extern __shared__ float qsm[];

    const int m0   = blockIdx.x * QBM;
    const int tid  = threadIdx.x;
    const int wid  = tid >> 5;
    const int lane = tid & 31;
    const int g    = lane >> 2;
    const int t4   = lane & 3;
    const int mrow = (wid & 3) * 16;
    const int wn   = wid >> 2;
    const int ncol = wn * 32;

    const uint32_t sm_u = (uint32_t)__cvta_generic_to_shared(qsm);

    uint32_t xoff[2];  const float* xsrc[2];
    #pragma unroll
    for (int i = 0; i < 2; ++i) {
        int c  = tid + i*256;
        int r  = c >> 3, cc = (c & 7) << 2;
        xoff[i] = (uint32_t)(r*LX + cc);
        xsrc[i] = X + (size_t)(m0 + r)*DIN + cc;
    }

    auto issueW = [&](int kt) {
        uint32_t base = sm_u + (uint32_t)(XTOT + (kt & 1)*WSTG)*4u;
        #pragma unroll
        for (int i = 0; i < 6; ++i) {
            int c   = tid + i*256;
            int mtx = c >> 9;
            int cw  = c & 511;
            uint32_t off = (uint32_t)(mtx*WMTX + (cw>>3)*36 + (cw&7)*4)*4u;
            cp16(base + off, g_wc[mtx] + (size_t)kt*2048 + (size_t)cw*4);
        }
        cp_commit();
    };
    auto issueX = [&](int kt) {
        uint32_t base = sm_u + (uint32_t)((kt % 3) * XSTG) * 4u;
        #pragma unroll
        for (int i = 0; i < 2; ++i)
            cp16(base + xoff[i]*4u, xsrc[i] + (size_t)kt*QBK);
        cp_commit();
    };

    float acc[3][4][4] = {};

    issueW(0);
    issueX(0);
    issueX(1);

    for (int j = 0; j < QNT; ++j) {
        cp_wait1();
        __syncthreads();

        if (j+1 < QNT) issueW(j+1);
        if (j+2 < QNT) issueX(j+2);

        const float* Xsp = qsm + (j % 3) * XSTG;
        const float* Wme = qsm + XTOT + (j & 1)*WSTG + (wn*32 + lane)*36;

        #pragma unroll
        for (int ks = 0; ks < 4; ++ks) {
            const int k0 = ks * 8;
            uint32_t a0 = __float_as_uint(tf32r(Xsp[(mrow+g  )*LX + k0 + t4    ]));
            uint32_t a1 = __float_as_uint(tf32r(Xsp[(mrow+g+8)*LX + k0 + t4    ]));
            uint32_t a2 = __float_as_uint(tf32r(Xsp[(mrow+g  )*LX + k0 + t4 + 4]));
            uint32_t a3 = __float_as_uint(tf32r(Xsp[(mrow+g+8)*LX + k0 + t4 + 4]));
            #pragma unroll
            for (int mtx = 0; mtx < 3; ++mtx) {
                const float* wr = Wme + mtx*WMTX + ks*8;
                float4 w0 = *reinterpret_cast<const float4*>(wr);
                float4 w1 = *reinterpret_cast<const float4*>(wr + 4);
                mma_tf32(acc[mtx][0], a0,a1,a2,a3, __float_as_uint(w0.x), __float_as_uint(w0.y));
                mma_tf32(acc[mtx][1], a0,a1,a2,a3, __float_as_uint(w0.z), __float_as_uint(w0.w));
                mma_tf32(acc[mtx][2], a0,a1,a2,a3, __float_as_uint(w1.x), __float_as_uint(w1.y));
                mma_tf32(acc[mtx][3], a0,a1,a2,a3, __float_as_uint(w1.z), __float_as_uint(w1.w));
            }
        }
    }

    #pragma unroll
    for (int nt = 0; nt < 4; ++nt) {
        int row = m0 + mrow + g;
        int col = ncol + nt*8 + 2*t4;
        float2 cA = {acc[0][nt][0], acc[0][nt][1]};
        float2 cB = {acc[0][nt][2], acc[0][nt][3]};
        *reinterpret_cast<float2*>(g_q + (size_t)row*DH + col)     = cA;
        *reinterpret_cast<float2*>(g_q + (size_t)(row+8)*DH + col) = cB;
    }

    float* Kt = g_k + (size_t)blockIdx.x * 4096;
    float* Vt = g_v + (size_t)blockIdx.x * 4096;
    const int keyA = mrow + g;
    const int keyB = keyA + 8;
    const int k7A = keyA & 7, k7B = keyB & 7;
    const int ksA = (k7A & 1) ? ((k7A + 7) >> 1) : (k7A >> 1);   // permuted slot
    const int ksB = (k7B & 1) ? ((k7B + 7) >> 1) : (k7B >> 1);
    #pragma unroll
    for (int nt = 0; nt < 4; ++nt) {
        #pragma unroll
        for (int e = 0; e < 2; ++e) {
            int d   = ncol + nt*8 + 2*t4 + e;
            int t4k = d & 3, bbk = (d >> 2) & 1, kskd = d >> 3;
            Kt[(size_t)((keyA & 7)*4 + t4k)*128 + kskd*16 + (keyA >> 3)*2 + bbk] = acc[1][nt][e];
            Kt[(size_t)((keyB & 7)*4 + t4k)*128 + kskd*16 + (keyB >> 3)*2 + bbk] = acc[1][nt][2+e];
            int gv = d & 7, ntv = d >> 3;
            Vt[(size_t)(gv*4 + (ksA & 3))*128 + (keyA >> 3)*16 + ntv*2 + ((ksA >> 2) & 1)] = tf32r(acc[2][nt][e]);
            Vt[(size_t)(gv*4 + (ksB & 3))*128 + (keyB >> 3)*16 + ntv*2 + ((ksB >> 2) & 1)] = tf32r(acc[2][nt][2+e]);
        }
    }
}

// ----------------------------------------------------------------------------
// Flash attention: 4 warps x 32 q-rows, NO P smem round-trip — the exp'd S
// accumulator IS the PV A-fragment ({c0,c2,c1,c3}) thanks to the permuted V
// layout. Softmax+PV fused per 32-key half (sc stays 32 regs). smem = K/V
// double-buffer only (67.6KB) -> 3 CTAs/SM. 1 syncthreads/tile, no syncwarp.
// ----------------------------------------------------------------------------
#define BQ   128
#define BKV  64
#define NTS  (SEQ/BKV/SPLIT)    // 16
#define KSTG (32*132)           // 4224 floats per stage
#define ATTN_SMEM_FLOATS (4*KSTG)
#define ATTN_SMEM_BYTES  (ATTN_SMEM_FLOATS*4)
#define QSCALE (0.125f * 1.44269504088896f)

__global__ __launch_bounds__(128,3)
void attn_kernel()
{
    extern __shared__ float sm[];
    float* Ks0 = sm;                   // [2][32 streams][132] raw f32
    float* Vs0 = Ks0 + 2*KSTG;         // [2][32 streams][132] RNA tf32, keys permuted

    const int b  = blockIdx.y >> 2;
    const int s  = blockIdx.y & 3;
    const int q0 = blockIdx.x * BQ;
    const float* __restrict__ Qb = g_q + ((size_t)b*SEQ + q0)*DH;
    const float* __restrict__ Kb = g_k + (size_t)(b*64 + s*16)*4096;
    const float* __restrict__ Vb = g_v + (size_t)(b*64 + s*16)*4096;

    const int tid  = threadIdx.x;
    const int wid  = tid >> 5;
    const int lane = tid & 31;
    const int g    = lane >> 2;
    const int t4   = lane & 3;
    const int r0   = wid*32 + g;

    const uint32_t ks_u = (uint32_t)__cvta_generic_to_shared(Ks0);
    const uint32_t vs_u = (uint32_t)__cvta_generic_to_shared(Vs0);

    // Q fragments for 2 row-pairs, pre-scaled by (1/8)*log2e
    uint32_t qf[8][8];
    #pragma unroll
    for (int ks = 0; ks < 8; ++ks) {
        const int k0 = ks * 8;
        #pragma unroll
        for (int rp = 0; rp < 2; ++rp) {
            const int ra = r0 + rp*16;
            qf[ks][rp*4+0] = __float_as_uint(Qb[(size_t)ra*DH      + k0 + t4    ] * QSCALE);
            qf[ks][rp*4+1] = __float_as_uint(Qb[(size_t)(ra+8)*DH  + k0 + t4    ] * QSCALE);
            qf[ks][rp*4+2] = __float_as_uint(Qb[(size_t)ra*DH      + k0 + t4 + 4] * QSCALE);
            qf[ks][rp*4+3] = __float_as_uint(Qb[(size_t)(ra+8)*DH  + k0 + t4 + 4] * QSCALE);
        }
    }

    // Prologue: stage tile 0
    #pragma unroll
    for (int it = 0; it < 8; ++it) {
        int c = tid + it*128;
        uint32_t off = (uint32_t)((c>>5)*132 + (c&31)*4)*4u;
        cp16(ks_u + off, Kb + (size_t)c*4);
        cp16(vs_u + off, Vb + (size_t)c*4);
    }
    cp_commit();
    cp_wait0();
    __syncthreads();

    float o[2][8][4] = {};
    float l0 = 0.f, l1 = 0.f, l2 = 0.f, l3 = 0.f;

    for (int j = 0; j < NTS; ++j) {
        const int p = j & 1;
        const float* kme = Ks0 + p*KSTG + lane*132;
        const float* vme = Vs0 + p*KSTG + lane*132;

        if (j+1 < NTS) {
            const float* Kn = Kb + (size_t)(j+1)*4096;
            const float* Vn = Vb + (size_t)(j+1)*4096;
            const uint32_t kd = ks_u + (uint32_t)((p^1)*KSTG)*4u;
            const uint32_t vd = vs_u + (uint32_t)((p^1)*KSTG)*4u;
            #pragma unroll
            for (int it = 0; it < 8; ++it) {
                int c = tid + it*128;
                uint32_t off = (uint32_t)((c>>5)*132 + (c&31)*4)*4u;
                cp16(kd + off, Kn + (size_t)c*4);
                cp16(vd + off, Vn + (size_t)c*4);
            }
            cp_commit();
        }

        #pragma unroll
        for (int half = 0; half < 2; ++half) {
            // ---- S for this 32-key half ----
            float sc[2][4][4] = {};
            #pragma unroll
            for (int ks = 0; ks < 8; ++ks) {
                const float* kr = kme + ks*16 + half*8;
                float4 w0 = *reinterpret_cast<const float4*>(kr);
                float4 w1 = *reinterpret_cast<const float4*>(kr + 4);
                #pragma unroll
                for (int rp = 0; rp < 2; ++rp) {
                    mma_tf32(sc[rp][0], qf[ks][rp*4],qf[ks][rp*4+1],qf[ks][rp*4+2],qf[ks][rp*4+3],
                             __float_as_uint(w0.x), __float_as_uint(w0.y));
                    mma_tf32(sc[rp][1], qf[ks][rp*4],qf[ks][rp*4+1],qf[ks][rp*4+2],qf[ks][rp*4+3],
                             __float_as_uint(w0.z), __float_as_uint(w0.w));
                    mma_tf32(sc[rp][2], qf[ks][rp*4],qf[ks][rp*4+1],qf[ks][rp*4+2],qf[ks][rp*4+3],
                             __float_as_uint(w1.x), __float_as_uint(w1.y));
                    mma_tf32(sc[rp][3], qf[ks][rp*4],qf[ks][rp*4+1],qf[ks][rp*4+2],qf[ks][rp*4+3],
                             __float_as_uint(w1.z), __float_as_uint(w1.w));
                }
            }

            // ---- softmax: exp in place, rearrange into A-frag order {c0,c2,c1,c3} ----
            #pragma unroll
            for (int rp = 0; rp < 2; ++rp) {
                #pragma unroll
                for (int ntl = 0; ntl < 4; ++ntl) {
                    float p0 = exp2f(sc[rp][ntl][0]);
                    float p1 = exp2f(sc[rp][ntl][1]);
                    float p2 = exp2f(sc[rp][ntl][2]);
                    float p3 = exp2f(sc[rp][ntl][3]);
                    if (rp == 0) { l0 += p0 + p1; l1 += p2 + p3; }
                    else         { l2 += p0 + p1; l3 += p2 + p3; }
                    sc[rp][ntl][0] = tf32r(p0);
                    sc[rp][ntl][1] = tf32r(p2);
                    sc[rp][ntl][2] = tf32r(p1);
                    sc[rp][ntl][3] = tf32r(p3);
                }
            }

            // ---- O += P V for this half's 4 key-chunks (A from registers) ----
            #pragma unroll
            for (int kc = 0; kc < 4; ++kc) {
                const float* vr = vme + (half*4 + kc)*16;
                float4 w0 = *reinterpret_cast<const float4*>(vr);
                float4 w1 = *reinterpret_cast<const float4*>(vr + 4);
                float4 w2 = *reinterpret_cast<const float4*>(vr + 8);
                float4 w3 = *reinterpret_cast<const float4*>(vr + 12);
                #pragma unroll
                for (int rp = 0; rp < 2; ++rp) {
                    float a0 = sc[rp][kc][0], a1 = sc[rp][kc][1];
                    float a2 = sc[rp][kc][2], a3 = sc[rp][kc][3];
                    mma_tf32f(o[rp][0], a0,a1,a2,a3, __float_as_uint(w0.x), __float_as_uint(w0.y));
                    mma_tf32f(o[rp][1], a0,a1,a2,a3, __float_as_uint(w0.z), __float_as_uint(w0.w));
                    mma_tf32f(o[rp][2], a0,a1,a2,a3, __float_as_uint(w1.x), __float_as_uint(w1.y));
                    mma_tf32f(o[rp][3], a0,a1,a2,a3, __float_as_uint(w1.z), __float_as_uint(w1.w));
                    mma_tf32f(o[rp][4], a0,a1,a2,a3, __float_as_uint(w2.x), __float_as_uint(w2.y));
                    mma_tf32f(o[rp][5], a0,a1,a2,a3, __float_as_uint(w2.z), __float_as_uint(w2.w));
                    mma_tf32f(o[rp][6], a0,a1,a2,a3, __float_as_uint(w3.x), __float_as_uint(w3.y));
                    mma_tf32f(o[rp][7], a0,a1,a2,a3, __float_as_uint(w3.z), __float_as_uint(w3.w));
                }
            }
        }

        cp_wait0();
        __syncthreads();
    }

    // Reduce l across quads
    l0 += __shfl_xor_sync(0xffffffffu, l0, 1);
    l0 += __shfl_xor_sync(0xffffffffu, l0, 2);
    l1 += __shfl_xor_sync(0xffffffffu, l1, 1);
    l1 += __shfl_xor_sync(0xffffffffu, l1, 2);
    l2 += __shfl_xor_sync(0xffffffffu, l2, 1);
    l2 += __shfl_xor_sync(0xffffffffu, l2, 2);
    l3 += __shfl_xor_sync(0xffffffffu, l3, 1);
    l3 += __shfl_xor_sync(0xffffffffu, l3, 2);

    float* Pob = g_po[s] + ((size_t)b*SEQ + q0)*DH;
    #pragma unroll
    for (int rp = 0; rp < 2; ++rp) {
        const int ra = r0 + rp*16;
        #pragma unroll
        for (int nt = 0; nt < 8; ++nt) {
            int col = nt*8 + 2*t4;
            float2 oa = {o[rp][nt][0], o[rp][nt][1]};
            float2 ob = {o[rp][nt][2], o[rp][nt][3]};
            *reinterpret_cast<float2*>(Pob + (size_t)ra*DH + col)     = oa;
            *reinterpret_cast<float2*>(Pob + (size_t)(ra+8)*DH + col) = ob;
        }
    }
    if (t4 == 0) {
        size_t base = (size_t)b*SEQ + q0;
        g_pl[s][base + r0]      = l0;
        g_pl[s][base + r0 + 8]  = l1;
        g_pl[s][base + r0 + 16] = l2;
        g_pl[s][base + r0 + 24] = l3;
    }
}

// ----------------------------------------------------------------------------
// Combine: out = sum(po)/sum(pl) over 4 splits
// ----------------------------------------------------------------------------
__global__ __launch_bounds__(256)
void combine_kernel(float* __restrict__ out)
{
    int t = blockIdx.x * 256 + threadIdx.x;
    int i0 = t * 2;
    int row = i0 >> 4;
    float l = g_pl[0][row] + g_pl[1][row] + g_pl[2][row] + g_pl[3][row];
    float inv = 1.0f / l;
    float4 r0 = {0,0,0,0}, r1 = {0,0,0,0};
    #pragma unroll
    for (int s = 0; s < SPLIT; ++s) {
        float4 a0 = reinterpret_cast<const float4*>(g_po[s])[i0];
        float4 a1 = reinterpret_cast<const float4*>(g_po[s])[i0+1];
        r0.x += a0.x; r0.y += a0.y; r0.z += a0.z; r0.w += a0.w;
        r1.x += a1.x; r1.y += a1.y; r1.z += a1.z; r1.w += a1.w;
    }
    r0.x *= inv; r0.y *= inv; r0.z *= inv; r0.w *= inv;
    r1.x *= inv; r1.y *= inv; r1.z *= inv; r1.w *= inv;
    reinterpret_cast<float4*>(out)[i0]   = r0;
    reinterpret_cast<float4*>(out)[i0+1] = r1;
}

// ----------------------------------------------------------------------------
extern "C" void kernel_launch(void* const* d_in, const int* in_sizes, int n_in,
                              void* d_out, int out_size)
{
    const float* x  = (const float*)d_in[0];
    const float* wq = (const float*)d_in[1];
    const float* wk = (const float*)d_in[2];
    const float* wv = (const float*)d_in[3];
    float* out = (float*)d_out;

    wconv_kernel<<<(DIN*DH)/256, 256>>>(wq, wk, wv);

    cudaFuncSetAttribute(qkv_gemm_kernel,
                         cudaFuncAttributeMaxDynamicSharedMemorySize,
                         QKV_SMEM_BYTES);
    qkv_gemm_kernel<<<MTOT / QBM, 256, QKV_SMEM_BYTES>>>(x);

    cudaFuncSetAttribute(attn_kernel,
                         cudaFuncAttributeMaxDynamicSharedMemorySize,
                         ATTN_SMEM_BYTES);
    dim3 ga(SEQ / BQ, SPLIT * BATCH);
    attn_kernel<<<ga, 128, ATTN_SMEM_BYTES>>>();

    combine_kernel<<<(MTOT*DH/8)/256, 256>>>(out);
}

// round 15
// speedup vs baseline: 1.2295x; 1.2295x over previous
#include <cuda_runtime.h>
#include <math_constants.h>
#include <cstdint>

#define BATCH 4
#define SEQ   4096
#define DIN   768
#define DH    64
#define MTOT  (BATCH*SEQ)
#define SPLIT 4

// Scratch (no cudaMalloc allowed)
// g_k fragment-stream layout per 64-key tile (4096 floats):
//   K element (key,d):  stream=(key&7)*4+(d&3),  pos=(d>>3)*16+((key&63)>>3)*2+((d>>2)&1)
// g_v: same but keys PERMUTED within each 8-group so the S accumulator is
//   directly the PV A-fragment: slot k for key: k = (key&1)? (key+7)>>1 : key>>1
__device__ float g_q[MTOT*DH];
__device__ float g_k[MTOT*DH];
__device__ float g_v[MTOT*DH];           // RNA-tf32 at producer
__device__ float g_wc[3][DIN*DH];        // RNA-tf32 weights, fragment-stream layout
__device__ float g_po[SPLIT][MTOT*DH];
__device__ float g_pl[SPLIT][MTOT];

__device__ __forceinline__ float tf32r(float x) {
    float r;
    asm("cvt.rna.tf32.f32 %0, %1;" : "=f"(r) : "f"(x));
    return r;
}

__device__ __forceinline__ void mma_tf32(float c[4],
                                         uint32_t a0, uint32_t a1, uint32_t a2, uint32_t a3,
                                         uint32_t b0, uint32_t b1) {
    asm volatile(
        "mma.sync.aligned.m16n8k8.row.col.f32.tf32.tf32.f32 "
        "{%0,%1,%2,%3},{%4,%5,%6,%7},{%8,%9},{%0,%1,%2,%3};\n"
        : "+f"(c[0]), "+f"(c[1]), "+f"(c[2]), "+f"(c[3])
        : "r"(a0), "r"(a1), "r"(a2), "r"(a3), "r"(b0), "r"(b1));
}

__device__ __forceinline__ void mma_tf32f(float c[4],
                                          float a0, float a1, float a2, float a3,
                                          uint32_t b0, uint32_t b1) {
    mma_tf32(c, __float_as_uint(a0), __float_as_uint(a1),
                __float_as_uint(a2), __float_as_uint(a3), b0, b1);
}

__device__ __forceinline__ void cp16(uint32_t dst, const float* src) {
    asm volatile("cp.async.ca.shared.global [%0], [%1], 16;\n" :: "r"(dst), "l"(src));
}
__device__ __forceinline__ void cp_commit() {
    asm volatile("cp.async.commit_group;\n");
}
__device__ __forceinline__ void cp_wait0() {
    asm volatile("cp.async.wait_group 0;\n" ::: "memory");
}
__device__ __forceinline__ void cp_wait1() {
    asm volatile("cp.async.wait_group 1;\n" ::: "memory");
}

// ----------------------------------------------------------------------------
// Weight pre-conversion + fragment-stream re-layout (unchanged).
// ----------------------------------------------------------------------------
__global__ __launch_bounds__(256)
void wconv_kernel(const float* __restrict__ wq,
                  const float* __restrict__ wk,
                  const float* __restrict__ wv)
{
    int i = blockIdx.x * 256 + threadIdx.x;
    const float* __restrict__ src[3] = {wq, wk, wv};
    int k  = i >> 6;
    int n  = i & 63;
    int kt = k >> 5, kk = k & 31;
    int ks = kk >> 3, t4w = kk & 3, bb = (kk >> 2) & 1;
    int wn = n >> 5, gg = n & 7, nt = (n >> 3) & 3;
    size_t dst = (size_t)kt*2048 + (size_t)(wn*32 + gg*4 + t4w)*32 + ks*8 + nt*2 + bb;
    #pragma unroll
    for (int m = 0; m < 3; ++m)
        g_wc[m][dst] = tf32r(src[m][i]);
}

// ----------------------------------------------------------------------------
// QKV projection (unchanged from r14): cp.async pipeline, W stream layout,
// epilogue scatters K (natural slots) and V (permuted slots), V RNA-rounded.
// ----------------------------------------------------------------------------
#define QBM 64
#define QBK 32
#define QNT (DIN/QBK)
#define LX  36
#define XSTG (QBM*LX)
#define WMTX (64*36)
#define WSTG (3*WMTX)
#define XTOT (3*XSTG)
#define QKV_SMEM_FLOATS (XTOT + 2*WSTG)
#define QKV_SMEM_BYTES  (QKV_SMEM_FLOATS*4)

__global__ __launch_bounds__(256)
void qkv_gemm_kernel(const float* __restrict__ X)
{
    extern __shared__ float qsm[];

    const int m0   = blockIdx.x * QBM;
    const int tid  = threadIdx.x;
    const int wid  = tid >> 5;
    const int lane = tid & 31;
    const int g    = lane >> 2;
    const int t4   = lane & 3;
    const int mrow = (wid & 3) * 16;
    const int wn   = wid >> 2;
    const int ncol = wn * 32;

    const uint32_t sm_u = (uint32_t)__cvta_generic_to_shared(qsm);

    uint32_t xoff[2];  const float* xsrc[2];
    #pragma unroll
    for (int i = 0; i < 2; ++i) {
        int c  = tid + i*256;
        int r  = c >> 3, cc = (c & 7) << 2;
        xoff[i] = (uint32_t)(r*LX + cc);
        xsrc[i] = X + (size_t)(m0 + r)*DIN + cc;
    }

    auto issueW = [&](int kt) {
        uint32_t base = sm_u + (uint32_t)(XTOT + (kt & 1)*WSTG)*4u;
        #pragma unroll
        for (int i = 0; i < 6; ++i) {
            int c   = tid + i*256;
            int mtx = c >> 9;
            int cw  = c & 511;
            uint32_t off = (uint32_t)(mtx*WMTX + (cw>>3)*36 + (cw&7)*4)*4u;
            cp16(base + off, g_wc[mtx] + (size_t)kt*2048 + (size_t)cw*4);
        }
        cp_commit();
    };
    auto issueX = [&](int kt) {
        uint32_t base = sm_u + (uint32_t)((kt % 3) * XSTG) * 4u;
        #pragma unroll
        for (int i = 0; i < 2; ++i)
            cp16(base + xoff[i]*4u, xsrc[i] + (size_t)kt*QBK);
        cp_commit();
    };

    float acc[3][4][4] = {};

    issueW(0);
    issueX(0);
    issueX(1);

    for (int j = 0; j < QNT; ++j) {
        cp_wait1();
        __syncthreads();

        if (j+1 < QNT) issueW(j+1);
        if (j+2 < QNT) issueX(j+2);

        const float* Xsp = qsm + (j % 3) * XSTG;
        const float* Wme = qsm + XTOT + (j & 1)*WSTG + (wn*32 + lane)*36;

        #pragma unroll
        for (int ks = 0; ks < 4; ++ks) {
            const int k0 = ks * 8;
            uint32_t a0 = __float_as_uint(tf32r(Xsp[(mrow+g  )*LX + k0 + t4    ]));
            uint32_t a1 = __float_as_uint(tf32r(Xsp[(mrow+g+8)*LX + k0 + t4    ]));
            uint32_t a2 = __float_as_uint(tf32r(Xsp[(mrow+g  )*LX + k0 + t4 + 4]));
            uint32_t a3 = __float_as_uint(tf32r(Xsp[(mrow+g+8)*LX + k0 + t4 + 4]));
            #pragma unroll
            for (int mtx = 0; mtx < 3; ++mtx) {
                const float* wr = Wme + mtx*WMTX + ks*8;
                float4 w0 = *reinterpret_cast<const float4*>(wr);
                float4 w1 = *reinterpret_cast<const float4*>(wr + 4);
                mma_tf32(acc[mtx][0], a0,a1,a2,a3, __float_as_uint(w0.x), __float_as_uint(w0.y));
                mma_tf32(acc[mtx][1], a0,a1,a2,a3, __float_as_uint(w0.z), __float_as_uint(w0.w));
                mma_tf32(acc[mtx][2], a0,a1,a2,a3, __float_as_uint(w1.x), __float_as_uint(w1.y));
                mma_tf32(acc[mtx][3], a0,a1,a2,a3, __float_as_uint(w1.z), __float_as_uint(w1.w));
            }
        }
    }

    #pragma unroll
    for (int nt = 0; nt < 4; ++nt) {
        int row = m0 + mrow + g;
        int col = ncol + nt*8 + 2*t4;
        float2 cA = {acc[0][nt][0], acc[0][nt][1]};
        float2 cB = {acc[0][nt][2], acc[0][nt][3]};
        *reinterpret_cast<float2*>(g_q + (size_t)row*DH + col)     = cA;
        *reinterpret_cast<float2*>(g_q + (size_t)(row+8)*DH + col) = cB;
    }

    float* Kt = g_k + (size_t)blockIdx.x * 4096;
    float* Vt = g_v + (size_t)blockIdx.x * 4096;
    const int keyA = mrow + g;
    const int keyB = keyA + 8;
    const int k7A = keyA & 7, k7B = keyB & 7;
    const int ksA = (k7A & 1) ? ((k7A + 7) >> 1) : (k7A >> 1);   // permuted slot
    const int ksB = (k7B & 1) ? ((k7B + 7) >> 1) : (k7B >> 1);
    #pragma unroll
    for (int nt = 0; nt < 4; ++nt) {
        #pragma unroll
        for (int e = 0; e < 2; ++e) {
            int d   = ncol + nt*8 + 2*t4 + e;
            int t4k = d & 3, bbk = (d >> 2) & 1, kskd = d >> 3;
            Kt[(size_t)((keyA & 7)*4 + t4k)*128 + kskd*16 + (keyA >> 3)*2 + bbk] = acc[1][nt][e];
            Kt[(size_t)((keyB & 7)*4 + t4k)*128 + kskd*16 + (keyB >> 3)*2 + bbk] = acc[1][nt][2+e];
            int gv = d & 7, ntv = d >> 3;
            Vt[(size_t)(gv*4 + (ksA & 3))*128 + (keyA >> 3)*16 + ntv*2 + ((ksA >> 2) & 1)] = tf32r(acc[2][nt][e]);
            Vt[(size_t)(gv*4 + (ksB & 3))*128 + (keyB >> 3)*16 + ntv*2 + ((ksB >> 2) & 1)] = tf32r(acc[2][nt][2+e]);
        }
    }
}

// ----------------------------------------------------------------------------
// Flash attention: r14 structure (P stays in registers; S accumulator IS the
// PV A-fragment via permuted V layout) but __launch_bounds__(128,2) so the
// 255-reg budget avoids the spills that sank r14's (128,3).
// ----------------------------------------------------------------------------
#define BQ   128
#define BKV  64
#define NTS  (SEQ/BKV/SPLIT)    // 16
#define KSTG (32*132)           // 4224 floats per stage
#define ATTN_SMEM_FLOATS (4*KSTG)
#define ATTN_SMEM_BYTES  (ATTN_SMEM_FLOATS*4)
#define QSCALE (0.125f * 1.44269504088896f)

__global__ __launch_bounds__(128,2)
void attn_kernel()
{
    extern __shared__ float sm[];
    float* Ks0 = sm;                   // [2][32 streams][132] raw f32
    float* Vs0 = Ks0 + 2*KSTG;         // [2][32 streams][132] RNA tf32, keys permuted

    const int b  = blockIdx.y >> 2;
    const int s  = blockIdx.y & 3;
    const int q0 = blockIdx.x * BQ;
    const float* __restrict__ Qb = g_q + ((size_t)b*SEQ + q0)*DH;
    const float* __restrict__ Kb = g_k + (size_t)(b*64 + s*16)*4096;
    const float* __restrict__ Vb = g_v + (size_t)(b*64 + s*16)*4096;

    const int tid  = threadIdx.x;
    const int wid  = tid >> 5;
    const int lane = tid & 31;
    const int g    = lane >> 2;
    const int t4   = lane & 3;
    const int r0   = wid*32 + g;

    const uint32_t ks_u = (uint32_t)__cvta_generic_to_shared(Ks0);
    const uint32_t vs_u = (uint32_t)__cvta_generic_to_shared(Vs0);

    // Q fragments for 2 row-pairs, pre-scaled by (1/8)*log2e
    uint32_t qf[8][8];
    #pragma unroll
    for (int ks = 0; ks < 8; ++ks) {
        const int k0 = ks * 8;
        #pragma unroll
        for (int rp = 0; rp < 2; ++rp) {
            const int ra = r0 + rp*16;
            qf[ks][rp*4+0] = __float_as_uint(Qb[(size_t)ra*DH      + k0 + t4    ] * QSCALE);
            qf[ks][rp*4+1] = __float_as_uint(Qb[(size_t)(ra+8)*DH  + k0 + t4    ] * QSCALE);
            qf[ks][rp*4+2] = __float_as_uint(Qb[(size_t)ra*DH      + k0 + t4 + 4] * QSCALE);
            qf[ks][rp*4+3] = __float_as_uint(Qb[(size_t)(ra+8)*DH  + k0 + t4 + 4] * QSCALE);
        }
    }

    // Prologue: stage tile 0
    #pragma unroll
    for (int it = 0; it < 8; ++it) {
        int c = tid + it*128;
        uint32_t off = (uint32_t)((c>>5)*132 + (c&31)*4)*4u;
        cp16(ks_u + off, Kb + (size_t)c*4);
        cp16(vs_u + off, Vb + (size_t)c*4);
    }
    cp_commit();
    cp_wait0();
    __syncthreads();

    float o[2][8][4] = {};
    float l0 = 0.f, l1 = 0.f, l2 = 0.f, l3 = 0.f;

    for (int j = 0; j < NTS; ++j) {
        const int p = j & 1;
        const float* kme = Ks0 + p*KSTG + lane*132;
        const float* vme = Vs0 + p*KSTG + lane*132;

        if (j+1 < NTS) {
            const float* Kn = Kb + (size_t)(j+1)*4096;
            const float* Vn = Vb + (size_t)(j+1)*4096;
            const uint32_t kd = ks_u + (uint32_t)((p^1)*KSTG)*4u;
            const uint32_t vd = vs_u + (uint32_t)((p^1)*KSTG)*4u;
            #pragma unroll
            for (int it = 0; it < 8; ++it) {
                int c = tid + it*128;
                uint32_t off = (uint32_t)((c>>5)*132 + (c&31)*4)*4u;
                cp16(kd + off, Kn + (size_t)c*4);
                cp16(vd + off, Vn + (size_t)c*4);
            }
            cp_commit();
        }

        #pragma unroll
        for (int half = 0; half < 2; ++half) {
            // ---- S for this 32-key half ----
            float sc[2][4][4] = {};
            #pragma unroll
            for (int ks = 0; ks < 8; ++ks) {
                const float* kr = kme + ks*16 + half*8;
                float4 w0 = *reinterpret_cast<const float4*>(kr);
                float4 w1 = *reinterpret_cast<const float4*>(kr + 4);
                #pragma unroll
                for (int rp = 0; rp < 2; ++rp) {
                    mma_tf32(sc[rp][0], qf[ks][rp*4],qf[ks][rp*4+1],qf[ks][rp*4+2],qf[ks][rp*4+3],
                             __float_as_uint(w0.x), __float_as_uint(w0.y));
                    mma_tf32(sc[rp][1], qf[ks][rp*4],qf[ks][rp*4+1],qf[ks][rp*4+2],qf[ks][rp*4+3],
                             __float_as_uint(w0.z), __float_as_uint(w0.w));
                    mma_tf32(sc[rp][2], qf[ks][rp*4],qf[ks][rp*4+1],qf[ks][rp*4+2],qf[ks][rp*4+3],
                             __float_as_uint(w1.x), __float_as_uint(w1.y));
                    mma_tf32(sc[rp][3], qf[ks][rp*4],qf[ks][rp*4+1],qf[ks][rp*4+2],qf[ks][rp*4+3],
                             __float_as_uint(w1.z), __float_as_uint(w1.w));
                }
            }

            // ---- softmax: exp in place, rearrange into A-frag order {c0,c2,c1,c3} ----
            #pragma unroll
            for (int rp = 0; rp < 2; ++rp) {
                #pragma unroll
                for (int ntl = 0; ntl < 4; ++ntl) {
                    float p0 = exp2f(sc[rp][ntl][0]);
                    float p1 = exp2f(sc[rp][ntl][1]);
                    float p2 = exp2f(sc[rp][ntl][2]);
                    float p3 = exp2f(sc[rp][ntl][3]);
                    if (rp == 0) { l0 += p0 + p1; l1 += p2 + p3; }
                    else         { l2 += p0 + p1; l3 += p2 + p3; }
                    sc[rp][ntl][0] = tf32r(p0);
                    sc[rp][ntl][1] = tf32r(p2);
                    sc[rp][ntl][2] = tf32r(p1);
                    sc[rp][ntl][3] = tf32r(p3);
                }
            }

            // ---- O += P V for this half's 4 key-chunks (A from registers) ----
            #pragma unroll
            for (int kc = 0; kc < 4; ++kc) {
                const float* vr = vme + (half*4 + kc)*16;
                float4 w0 = *reinterpret_cast<const float4*>(vr);
                float4 w1 = *reinterpret_cast<const float4*>(vr + 4);
                float4 w2 = *reinterpret_cast<const float4*>(vr + 8);
                float4 w3 = *reinterpret_cast<const float4*>(vr + 12);
                #pragma unroll
                for (int rp = 0; rp < 2; ++rp) {
                    float a0 = sc[rp][kc][0], a1 = sc[rp][kc][1];
                    float a2 = sc[rp][kc][2], a3 = sc[rp][kc][3];
                    mma_tf32f(o[rp][0], a0,a1,a2,a3, __float_as_uint(w0.x), __float_as_uint(w0.y));
                    mma_tf32f(o[rp][1], a0,a1,a2,a3, __float_as_uint(w0.z), __float_as_uint(w0.w));
                    mma_tf32f(o[rp][2], a0,a1,a2,a3, __float_as_uint(w1.x), __float_as_uint(w1.y));
                    mma_tf32f(o[rp][3], a0,a1,a2,a3, __float_as_uint(w1.z), __float_as_uint(w1.w));
                    mma_tf32f(o[rp][4], a0,a1,a2,a3, __float_as_uint(w2.x), __float_as_uint(w2.y));
                    mma_tf32f(o[rp][5], a0,a1,a2,a3, __float_as_uint(w2.z), __float_as_uint(w2.w));
                    mma_tf32f(o[rp][6], a0,a1,a2,a3, __float_as_uint(w3.x), __float_as_uint(w3.y));
                    mma_tf32f(o[rp][7], a0,a1,a2,a3, __float_as_uint(w3.z), __float_as_uint(w3.w));
                }
            }
        }

        cp_wait0();
        __syncthreads();
    }

    // Reduce l across quads
    l0 += __shfl_xor_sync(0xffffffffu, l0, 1);
    l0 += __shfl_xor_sync(0xffffffffu, l0, 2);
    l1 += __shfl_xor_sync(0xffffffffu, l1, 1);
    l1 += __shfl_xor_sync(0xffffffffu, l1, 2);
    l2 += __shfl_xor_sync(0xffffffffu, l2, 1);
    l2 += __shfl_xor_sync(0xffffffffu, l2, 2);
    l3 += __shfl_xor_sync(0xffffffffu, l3, 1);
    l3 += __shfl_xor_sync(0xffffffffu, l3, 2);

    float* Pob = g_po[s] + ((size_t)b*SEQ + q0)*DH;
    #pragma unroll
    for (int rp = 0; rp < 2; ++rp) {
        const int ra = r0 + rp*16;
        #pragma unroll
        for (int nt = 0; nt < 8; ++nt) {
            int col = nt*8 + 2*t4;
            float2 oa = {o[rp][nt][0], o[rp][nt][1]};
            float2 ob = {o[rp][nt][2], o[rp][nt][3]};
            *reinterpret_cast<float2*>(Pob + (size_t)ra*DH + col)     = oa;
            *reinterpret_cast<float2*>(Pob + (size_t)(ra+8)*DH + col) = ob;
        }
    }
    if (t4 == 0) {
        size_t base = (size_t)b*SEQ + q0;
        g_pl[s][base + r0]      = l0;
        g_pl[s][base + r0 + 8]  = l1;
        g_pl[s][base + r0 + 16] = l2;
        g_pl[s][base + r0 + 24] = l3;
    }
}

// ----------------------------------------------------------------------------
// Combine: out = sum(po)/sum(pl) over 4 splits
// ----------------------------------------------------------------------------
__global__ __launch_bounds__(256)
void combine_kernel(float* __restrict__ out)
{
    int t = blockIdx.x * 256 + threadIdx.x;
    int i0 = t * 2;
    int row = i0 >> 4;
    float l = g_pl[0][row] + g_pl[1][row] + g_pl[2][row] + g_pl[3][row];
    float inv = 1.0f / l;
    float4 r0 = {0,0,0,0}, r1 = {0,0,0,0};
    #pragma unroll
    for (int s = 0; s < SPLIT; ++s) {
        float4 a0 = reinterpret_cast<const float4*>(g_po[s])[i0];
        float4 a1 = reinterpret_cast<const float4*>(g_po[s])[i0+1];
        r0.x += a0.x; r0.y += a0.y; r0.z += a0.z; r0.w += a0.w;
        r1.x += a1.x; r1.y += a1.y; r1.z += a1.z; r1.w += a1.w;
    }
    r0.x *= inv; r0.y *= inv; r0.z *= inv; r0.w *= inv;
    r1.x *= inv; r1.y *= inv; r1.z *= inv; r1.w *= inv;
    reinterpret_cast<float4*>(out)[i0]   = r0;
    reinterpret_cast<float4*>(out)[i0+1] = r1;
}

// ----------------------------------------------------------------------------
extern "C" void kernel_launch(void* const* d_in, const int* in_sizes, int n_in,
                              void* d_out, int out_size)
{
    const float* x  = (const float*)d_in[0];
    const float* wq = (const float*)d_in[1];
    const float* wk = (const float*)d_in[2];
    const float* wv = (const float*)d_in[3];
    float* out = (float*)d_out;

    wconv_kernel<<<(DIN*DH)/256, 256>>>(wq, wk, wv);

    cudaFuncSetAttribute(qkv_gemm_kernel,
                         cudaFuncAttributeMaxDynamicSharedMemorySize,
                         QKV_SMEM_BYTES);
    qkv_gemm_kernel<<<MTOT / QBM, 256, QKV_SMEM_BYTES>>>(x);

    cudaFuncSetAttribute(attn_kernel,
                         cudaFuncAttributeMaxDynamicSharedMemorySize,
                         ATTN_SMEM_BYTES);
    dim3 ga(SEQ / BQ, SPLIT * BATCH);
    attn_kernel<<<ga, 128, ATTN_SMEM_BYTES>>>();

    combine_kernel<<<(MTOT*DH/8)/256, 256>>>(out);
}